// round 2
// baseline (speedup 1.0000x reference)
#include <cuda_runtime.h>

#define D 128
#define NG 64
#define CO 16
#define MAXN 50176
#define NEG 0.1f
#define XSS 129   // padded row stride for xs (rows 8 apart land on different banks)

// -------- scratch (device globals: allocation-free workaround) --------
__device__ float g_h1[MAXN * D];
__device__ float g_h2[MAXN * D];
__device__ float g_agg[MAXN * D];
__device__ float g_deg[MAXN];
__device__ float g_dinv[MAXN];
__device__ float g_pool[NG * D];
__device__ float g_cnt[NG];

__device__ __forceinline__ float lrelu(float v) {
    return v >= 0.0f ? v : NEG * v;
}

// -------- init: zero agg/pool/cnt, deg = 1 (self-loop) --------
__global__ void k_init(int n) {
    int stride = gridDim.x * blockDim.x;
    int i0 = blockIdx.x * blockDim.x + threadIdx.x;
    int tot = n * D;
    for (int i = i0; i < tot; i += stride) g_agg[i] = 0.0f;
    for (int i = i0; i < n; i += stride) g_deg[i] = 1.0f;
    for (int i = i0; i < NG * D; i += stride) g_pool[i] = 0.0f;
    for (int i = i0; i < NG; i += stride) g_cnt[i] = 0.0f;
}

// -------- degree over dst --------
__global__ void k_deg(const int* __restrict__ dst, int E) {
    int stride = gridDim.x * blockDim.x;
    for (int e = blockIdx.x * blockDim.x + threadIdx.x; e < E; e += stride)
        atomicAdd(&g_deg[dst[e]], 1.0f);
}

__global__ void k_dinv(int n) {
    int i = blockIdx.x * blockDim.x + threadIdx.x;
    if (i < n) g_dinv[i] = rsqrtf(g_deg[i]);
}

// -------- GEMM: out[n,128] = A[n,128] @ W[128,128] --------
// 128 threads/block, tile = 64 rows x 128 cols. Each thread: 8 rows x 8 cols
// via packed fma.rn.f32x2 (32 FFMA2 per k). W in SMEM (64KB), x tile in SMEM
// with padded stride. 2 CTAs/SM.
__global__ void __launch_bounds__(128, 2)
k_gemm(const float* __restrict__ A, const float* __restrict__ W,
       float* __restrict__ out, int n) {
    extern __shared__ float sm[];
    float* Ws = sm;            // 128*128 floats (64KB)
    float* xs = sm + D * D;    // 64 * XSS floats

    int t = threadIdx.x;
    for (int i = t; i < (D * D) / 4; i += 128)
        ((float4*)Ws)[i] = ((const float4*)W)[i];

    int r0 = blockIdx.x * 64;
    int rows = n - r0;
    if (rows > 64) rows = 64;

    // stage x tile: coalesced float4 loads, scalar stores into padded layout
    for (int i = t; i < rows * 32; i += 128) {
        int row = i >> 5, c4 = i & 31;
        float4 v = ((const float4*)(A + (size_t)(r0 + row) * D))[c4];
        float* p = &xs[row * XSS + c4 * 4];
        p[0] = v.x; p[1] = v.y; p[2] = v.z; p[3] = v.w;
    }
    __syncthreads();

    int tc = t & 15;    // col group: cols tc*8 .. tc*8+7
    int tr = t >> 4;    // row group: rows tr*8 .. tr*8+7
    const float* xrow = &xs[tr * 8 * XSS];

    unsigned long long acc[8][4];
    #pragma unroll
    for (int r = 0; r < 8; r++)
        #pragma unroll
        for (int p = 0; p < 4; p++) acc[r][p] = 0ull;

    #pragma unroll 2
    for (int k = 0; k < D; k++) {
        // 8 weight floats = 4 packed f32x2 operands (ready-paired in smem)
        ulonglong2 wA = *(const ulonglong2*)&Ws[k * D + tc * 8];
        ulonglong2 wB = *(const ulonglong2*)&Ws[k * D + tc * 8 + 4];
        #pragma unroll
        for (int r = 0; r < 8; r++) {
            float xv = xrow[r * XSS + k];
            unsigned long long xx;
            asm("mov.b64 %0, {%1,%1};" : "=l"(xx) : "f"(xv));
            asm("fma.rn.f32x2 %0, %1, %2, %0;" : "+l"(acc[r][0]) : "l"(xx), "l"(wA.x));
            asm("fma.rn.f32x2 %0, %1, %2, %0;" : "+l"(acc[r][1]) : "l"(xx), "l"(wA.y));
            asm("fma.rn.f32x2 %0, %1, %2, %0;" : "+l"(acc[r][2]) : "l"(xx), "l"(wB.x));
            asm("fma.rn.f32x2 %0, %1, %2, %0;" : "+l"(acc[r][3]) : "l"(xx), "l"(wB.y));
        }
    }

    float* obase = out + (size_t)r0 * D + tc * 8;
    #pragma unroll
    for (int r = 0; r < 8; r++) {
        int row = tr * 8 + r;
        if (row < rows) {
            float o0, o1, o2, o3, o4, o5, o6, o7;
            asm("mov.b64 {%0,%1}, %2;" : "=f"(o0), "=f"(o1) : "l"(acc[r][0]));
            asm("mov.b64 {%0,%1}, %2;" : "=f"(o2), "=f"(o3) : "l"(acc[r][1]));
            asm("mov.b64 {%0,%1}, %2;" : "=f"(o4), "=f"(o5) : "l"(acc[r][2]));
            asm("mov.b64 {%0,%1}, %2;" : "=f"(o6), "=f"(o7) : "l"(acc[r][3]));
            *(float4*)&obase[(size_t)row * D]     = make_float4(o0, o1, o2, o3);
            *(float4*)&obase[(size_t)row * D + 4] = make_float4(o4, o5, o6, o7);
        }
    }
}

// -------- edge scatter: agg[dst] += coef * h[src], warp per edge --------
__global__ void k_scatter(const float* __restrict__ h, const int* __restrict__ src,
                          const int* __restrict__ dst, int E) {
    int e = blockIdx.x * 8 + (threadIdx.x >> 5);
    if (e >= E) return;
    int lane = threadIdx.x & 31;
    int s = src[e], d = dst[e];
    float coef = g_dinv[s] * g_dinv[d];
    float4 v = ((const float4*)(h + (size_t)s * D))[lane];
    float4 w = make_float4(v.x * coef, v.y * coef, v.z * coef, v.w * coef);
    atomicAdd(((float4*)(g_agg + (size_t)d * D)) + lane, w);
}

// -------- combine: h = leaky(agg + h*dinv^2 + b), in place; zero agg --------
__global__ void k_combine(float* __restrict__ h, const float* __restrict__ bias, int n) {
    int stride = gridDim.x * blockDim.x;
    int tot = n * (D / 4);
    float4* agg4 = (float4*)g_agg;
    float4* h4 = (float4*)h;
    const float4* b4 = (const float4*)bias;
    const float4 z = make_float4(0.f, 0.f, 0.f, 0.f);
    for (int i = blockIdx.x * blockDim.x + threadIdx.x; i < tot; i += stride) {
        int node = i >> 5;
        int f4 = i & 31;
        float di = g_dinv[node];
        float d2 = di * di;
        float4 a = agg4[i], hv = h4[i], b = b4[f4];
        float4 r;
        r.x = lrelu(a.x + hv.x * d2 + b.x);
        r.y = lrelu(a.y + hv.y * d2 + b.y);
        r.z = lrelu(a.z + hv.z * d2 + b.z);
        r.w = lrelu(a.w + hv.w * d2 + b.w);
        h4[i] = r;
        agg4[i] = z;  // re-zero for layer 2 (replaces separate kernel)
    }
}

// -------- layer-2 combine + global mean pool (sum + count via atomics) --------
__global__ void k_pool(const float* __restrict__ h, const float* __restrict__ bias,
                       const int* __restrict__ batch, int n) {
    int node = blockIdx.x * 8 + (threadIdx.x >> 5);
    if (node >= n) return;
    int lane = threadIdx.x & 31;
    float di = g_dinv[node];
    float d2 = di * di;
    float4 a = ((const float4*)g_agg)[node * 32 + lane];
    float4 hv = ((const float4*)h)[node * 32 + lane];
    float4 b = ((const float4*)bias)[lane];
    float4 v;
    v.x = lrelu(a.x + hv.x * d2 + b.x);
    v.y = lrelu(a.y + hv.y * d2 + b.y);
    v.z = lrelu(a.z + hv.z * d2 + b.z);
    v.w = lrelu(a.w + hv.w * d2 + b.w);
    int gid = batch[node];
    atomicAdd(((float4*)g_pool) + gid * 32 + lane, v);
    if (lane == 0) atomicAdd(&g_cnt[gid], 1.0f);
}

// -------- head: out[g,c] = (pool[g]/cnt[g]) @ Wl + bl --------
__global__ void k_final(const float* __restrict__ Wl, const float* __restrict__ bl,
                        float* __restrict__ out) {
    int t = threadIdx.x;           // 1024 threads, 1 block
    int g = t >> 4;
    int c = t & 15;
    float cnt = fmaxf(g_cnt[g], 1.0f);
    float s = 0.0f;
    #pragma unroll 8
    for (int f = 0; f < D; f++)
        s += g_pool[g * D + f] * Wl[f * CO + c];
    out[g * CO + c] = s / cnt + bl[c];
}

extern "C" void kernel_launch(void* const* d_in, const int* in_sizes, int n_in,
                              void* d_out, int out_size) {
    const float* x     = (const float*)d_in[0];
    const int*   ei    = (const int*)d_in[1];
    const int*   batch = (const int*)d_in[2];
    const float* W1    = (const float*)d_in[3];
    const float* b1    = (const float*)d_in[4];
    const float* W2    = (const float*)d_in[5];
    const float* b2    = (const float*)d_in[6];
    const float* Wl    = (const float*)d_in[7];
    const float* bl    = (const float*)d_in[8];

    int n = in_sizes[0] / D;
    int E = in_sizes[1] / 2;
    const int* src = ei;
    const int* dst = ei + E;

    void *ph1 = nullptr, *ph2 = nullptr;
    cudaGetSymbolAddress(&ph1, g_h1);
    cudaGetSymbolAddress(&ph2, g_h2);
    float* h1 = (float*)ph1;
    float* h2 = (float*)ph2;

    int smem = (D * D + 64 * XSS) * (int)sizeof(float);  // 98560 B
    cudaFuncSetAttribute(k_gemm, cudaFuncAttributeMaxDynamicSharedMemorySize, smem);

    int gblocks = (n + 63) / 64;
    int eblocks = (E + 7) / 8;

    k_init<<<2048, 256>>>(n);
    k_deg<<<1024, 256>>>(dst, E);
    k_dinv<<<(n + 255) / 256, 256>>>(n);

    // Layer 1
    k_gemm<<<gblocks, 128, smem>>>(x, W1, h1, n);
    k_scatter<<<eblocks, 256>>>(h1, src, dst, E);
    k_combine<<<2048, 256>>>(h1, b1, n);   // also re-zeroes g_agg

    // Layer 2
    k_gemm<<<gblocks, 128, smem>>>(h1, W2, h2, n);
    k_scatter<<<eblocks, 256>>>(h2, src, dst, E);
    k_pool<<<(n + 7) / 8, 256>>>(h2, b2, batch, n);

    // Head
    k_final<<<1, 1024>>>(Wl, bl, (float*)d_out);
}

// round 3
// speedup vs baseline: 1.3525x; 1.3525x over previous
#include <cuda_runtime.h>

#define D 128
#define NG 64
#define CO 16
#define MAXN 50176
#define MAXE 600064
#define NEG 0.1f

// -------- scratch (device globals: allocation-free workaround) --------
__device__ float g_h1[MAXN * D];
__device__ float g_h2[MAXN * D];
__device__ float g_dinv[MAXN];
__device__ int   g_degi[MAXN];
__device__ int   g_rowptr[MAXN + 1];
__device__ int   g_fill[MAXN];
__device__ int   g_csr_src[MAXE];
__device__ float g_pool[NG * D];
__device__ float g_cnt[NG];

__device__ __forceinline__ float lrelu(float v) {
    return v >= 0.0f ? v : NEG * v;
}

// -------- init: zero degi / pool / cnt --------
__global__ void k_init(int n) {
    int stride = gridDim.x * blockDim.x;
    int i0 = blockIdx.x * blockDim.x + threadIdx.x;
    for (int i = i0; i < n; i += stride) g_degi[i] = 0;
    for (int i = i0; i < NG * D; i += stride) g_pool[i] = 0.0f;
    for (int i = i0; i < NG; i += stride) g_cnt[i] = 0.0f;
}

// -------- int histogram over dst --------
__global__ void k_hist(const int* __restrict__ dst, int E) {
    int stride = gridDim.x * blockDim.x;
    for (int e = blockIdx.x * blockDim.x + threadIdx.x; e < E; e += stride)
        atomicAdd(&g_degi[dst[e]], 1);
}

// -------- single-block exclusive scan -> rowptr, fill, dinv; graph counts --------
__global__ void k_scan(const int* __restrict__ batch, int n) {
    __shared__ int part[1024];
    int t = threadIdx.x;
    int chunk = (n + 1023) / 1024;
    int b = t * chunk;
    int e = b + chunk; if (e > n) e = n;

    int s = 0;
    for (int i = b; i < e; i++) s += g_degi[i];
    part[t] = s;
    __syncthreads();
    // Hillis-Steele inclusive scan over 1024 partials
    for (int off = 1; off < 1024; off <<= 1) {
        int v = (t >= off) ? part[t - off] : 0;
        __syncthreads();
        part[t] += v;
        __syncthreads();
    }
    int excl = (t == 0) ? 0 : part[t - 1];
    for (int i = b; i < e; i++) {
        int d = g_degi[i];
        g_rowptr[i] = excl;
        g_fill[i] = excl;
        excl += d;
        g_dinv[i] = rsqrtf((float)d + 1.0f);   // +1 self-loop
        atomicAdd(&g_cnt[batch[i]], 1.0f);
    }
    if (t == 1023) g_rowptr[n] = part[1023];
}

// -------- permute edges into CSR (by dst) --------
__global__ void k_permute(const int* __restrict__ src, const int* __restrict__ dst, int E) {
    int stride = gridDim.x * blockDim.x;
    for (int e = blockIdx.x * blockDim.x + threadIdx.x; e < E; e += stride) {
        int d = dst[e];
        int pos = atomicAdd(&g_fill[d], 1);
        g_csr_src[pos] = src[e];
    }
}

// -------- GEMM: out[n,128] = A[n,128] @ W[128,128] (round-1 version) --------
__global__ void k_gemm(const float* __restrict__ A, const float* __restrict__ W,
                       float* __restrict__ out, int n) {
    extern __shared__ float sm[];
    float* Ws = sm;            // 128*128
    float* xs = sm + D * D;    // 16*128
    int t = threadIdx.x;
    for (int i = t; i < (D * D) / 4; i += 128)
        ((float4*)Ws)[i] = ((const float4*)W)[i];
    __syncthreads();

    int lane = t & 31;
    int wg = t >> 5;
    int col = lane * 4;
    int rb = wg * 4;

    for (int r0 = blockIdx.x * 16; r0 < n; r0 += gridDim.x * 16) {
        int rows = n - r0;
        if (rows > 16) rows = 16;
        __syncthreads();
        for (int i = t; i < rows * (D / 4); i += 128)
            ((float4*)xs)[i] = ((const float4*)(A + (size_t)r0 * D))[i];
        __syncthreads();

        float4 a0 = {0,0,0,0}, a1 = {0,0,0,0}, a2 = {0,0,0,0}, a3 = {0,0,0,0};
        #pragma unroll 4
        for (int k = 0; k < D; k++) {
            float4 w = *(const float4*)&Ws[k * D + col];
            float x0 = xs[(rb + 0) * D + k];
            float x1 = xs[(rb + 1) * D + k];
            float x2 = xs[(rb + 2) * D + k];
            float x3 = xs[(rb + 3) * D + k];
            a0.x += x0 * w.x; a0.y += x0 * w.y; a0.z += x0 * w.z; a0.w += x0 * w.w;
            a1.x += x1 * w.x; a1.y += x1 * w.y; a1.z += x1 * w.z; a1.w += x1 * w.w;
            a2.x += x2 * w.x; a2.y += x2 * w.y; a2.z += x2 * w.z; a2.w += x2 * w.w;
            a3.x += x3 * w.x; a3.y += x3 * w.y; a3.z += x3 * w.z; a3.w += x3 * w.w;
        }
        if (rb + 0 < rows) *(float4*)&out[(size_t)(r0 + rb + 0) * D + col] = a0;
        if (rb + 1 < rows) *(float4*)&out[(size_t)(r0 + rb + 1) * D + col] = a1;
        if (rb + 2 < rows) *(float4*)&out[(size_t)(r0 + rb + 2) * D + col] = a2;
        if (rb + 3 < rows) *(float4*)&out[(size_t)(r0 + rb + 3) * D + col] = a3;
    }
}

// -------- CSR gather + combine: out = lrelu(sum coef*h[src] + h*dinv^2 + b) ----
// one warp per dst node; lane owns 4 features.
__global__ void k_gcn(const float* __restrict__ h, const float* __restrict__ bias,
                      float* __restrict__ out, int n) {
    int node = blockIdx.x * 8 + (threadIdx.x >> 5);
    if (node >= n) return;
    int lane = threadIdx.x & 31;
    int beg = g_rowptr[node], end = g_rowptr[node + 1];
    float di = g_dinv[node];

    float4 acc = make_float4(0.f, 0.f, 0.f, 0.f);
    for (int e = beg; e < end; e++) {
        int s = g_csr_src[e];                 // broadcast load
        float coef = g_dinv[s] * di;          // broadcast load
        float4 v = ((const float4*)(h + (size_t)s * D))[lane];
        acc.x += coef * v.x; acc.y += coef * v.y;
        acc.z += coef * v.z; acc.w += coef * v.w;
    }
    float4 hv = ((const float4*)(h + (size_t)node * D))[lane];
    float4 b = ((const float4*)bias)[lane];
    float d2 = di * di;
    float4 r;
    r.x = lrelu(acc.x + hv.x * d2 + b.x);
    r.y = lrelu(acc.y + hv.y * d2 + b.y);
    r.z = lrelu(acc.z + hv.z * d2 + b.z);
    r.w = lrelu(acc.w + hv.w * d2 + b.w);
    ((float4*)(out + (size_t)node * D))[lane] = r;
}

// -------- layer-2: CSR gather + combine + pool atomics --------
__global__ void k_gcn_pool(const float* __restrict__ h, const float* __restrict__ bias,
                           const int* __restrict__ batch, int n) {
    int node = blockIdx.x * 8 + (threadIdx.x >> 5);
    if (node >= n) return;
    int lane = threadIdx.x & 31;
    int beg = g_rowptr[node], end = g_rowptr[node + 1];
    float di = g_dinv[node];

    float4 acc = make_float4(0.f, 0.f, 0.f, 0.f);
    for (int e = beg; e < end; e++) {
        int s = g_csr_src[e];
        float coef = g_dinv[s] * di;
        float4 v = ((const float4*)(h + (size_t)s * D))[lane];
        acc.x += coef * v.x; acc.y += coef * v.y;
        acc.z += coef * v.z; acc.w += coef * v.w;
    }
    float4 hv = ((const float4*)(h + (size_t)node * D))[lane];
    float4 b = ((const float4*)bias)[lane];
    float d2 = di * di;
    float4 r;
    r.x = lrelu(acc.x + hv.x * d2 + b.x);
    r.y = lrelu(acc.y + hv.y * d2 + b.y);
    r.z = lrelu(acc.z + hv.z * d2 + b.z);
    r.w = lrelu(acc.w + hv.w * d2 + b.w);
    int gid = batch[node];
    atomicAdd(((float4*)g_pool) + gid * 32 + lane, r);
}

// -------- head: out[g,c] = (pool[g]/cnt[g]) @ Wl + bl --------
__global__ void k_final(const float* __restrict__ Wl, const float* __restrict__ bl,
                        float* __restrict__ out) {
    int t = threadIdx.x;           // 1024 threads, 1 block
    int g = t >> 4;
    int c = t & 15;
    float cnt = fmaxf(g_cnt[g], 1.0f);
    float s = 0.0f;
    #pragma unroll 8
    for (int f = 0; f < D; f++)
        s += g_pool[g * D + f] * Wl[f * CO + c];
    out[g * CO + c] = s / cnt + bl[c];
}

extern "C" void kernel_launch(void* const* d_in, const int* in_sizes, int n_in,
                              void* d_out, int out_size) {
    const float* x     = (const float*)d_in[0];
    const int*   ei    = (const int*)d_in[1];
    const int*   batch = (const int*)d_in[2];
    const float* W1    = (const float*)d_in[3];
    const float* b1    = (const float*)d_in[4];
    const float* W2    = (const float*)d_in[5];
    const float* b2    = (const float*)d_in[6];
    const float* Wl    = (const float*)d_in[7];
    const float* bl    = (const float*)d_in[8];

    int n = in_sizes[0] / D;
    int E = in_sizes[1] / 2;
    const int* src = ei;
    const int* dst = ei + E;

    void *ph1 = nullptr, *ph2 = nullptr;
    cudaGetSymbolAddress(&ph1, g_h1);
    cudaGetSymbolAddress(&ph2, g_h2);
    float* h1 = (float*)ph1;
    float* h2 = (float*)ph2;

    int smem = (D * D + 16 * D) * (int)sizeof(float);  // 73728 B
    cudaFuncSetAttribute(k_gemm, cudaFuncAttributeMaxDynamicSharedMemorySize, smem);

    int nblocks8 = (n + 7) / 8;

    // CSR build
    k_init<<<1024, 256>>>(n);
    k_hist<<<1024, 256>>>(dst, E);
    k_scan<<<1, 1024>>>(batch, n);
    k_permute<<<1024, 256>>>(src, dst, E);

    // Layer 1: h1 = x@W1 ; h2 = gcn(h1)
    k_gemm<<<444, 128, smem>>>(x, W1, h1, n);
    k_gcn<<<nblocks8, 256>>>(h1, b1, h2, n);

    // Layer 2: h1 = h2@W2 ; pool += gcn(h1)
    k_gemm<<<444, 128, smem>>>(h2, W2, h1, n);
    k_gcn_pool<<<nblocks8, 256>>>(h1, b2, batch, n);

    // Head
    k_final<<<1, 1024>>>(Wl, bl, (float*)d_out);
}

// round 4
// speedup vs baseline: 1.8415x; 1.3615x over previous
#include <cuda_runtime.h>

#define D 128
#define NG 64
#define CO 16
#define MAXN 50176
#define MAXE 600064
#define NEG 0.1f
#define SCAN_CHUNK 1024
#define MAXBLK ((MAXN + SCAN_CHUNK - 1) / SCAN_CHUNK)   // 49

// -------- scratch (device globals: allocation-free workaround) --------
__device__ float g_h1[MAXN * D];
__device__ float g_h2[MAXN * D];
__device__ float g_dinv[MAXN];
__device__ int   g_degi[MAXN];
__device__ int   g_rowptr[MAXN + 1];
__device__ int   g_fill[MAXN];
__device__ int   g_csr_src[MAXE];
__device__ int   g_part[64];          // block partial sums (exclusive offsets after kB)
__device__ float g_pool[NG * D];
__device__ float g_cnt[NG];

__device__ __forceinline__ float lrelu(float v) {
    return v >= 0.0f ? v : NEG * v;
}

// -------- init: zero degi / pool / cnt --------
__global__ void k_init(const int* __restrict__ batch, int n) {
    int stride = gridDim.x * blockDim.x;
    int i0 = blockIdx.x * blockDim.x + threadIdx.x;
    for (int i = i0; i < n; i += stride) g_degi[i] = 0;
    for (int i = i0; i < NG * D; i += stride) g_pool[i] = 0.0f;
    for (int i = i0; i < NG; i += stride) g_cnt[i] = 0.0f;
}

// -------- int histogram over dst --------
__global__ void k_hist(const int* __restrict__ dst, int E) {
    int stride = gridDim.x * blockDim.x;
    for (int e = blockIdx.x * blockDim.x + threadIdx.x; e < E; e += stride)
        atomicAdd(&g_degi[dst[e]], 1);
}

// -------- graph node counts (grid-wide, distributed atomics) --------
__global__ void k_cnt(const int* __restrict__ batch, int n) {
    int stride = gridDim.x * blockDim.x;
    for (int i = blockIdx.x * blockDim.x + threadIdx.x; i < n; i += stride)
        atomicAdd(&g_cnt[batch[i]], 1.0f);
}

// -------- scan phase A: per-block sums of 1024-chunks --------
__global__ void k_scanA(int n) {
    __shared__ int red[8];
    int t = threadIdx.x;              // 256 threads
    int base = blockIdx.x * SCAN_CHUNK;
    int s = 0;
    #pragma unroll
    for (int j = 0; j < 4; j++) {
        int i = base + t + j * 256;
        if (i < n) s += g_degi[i];
    }
    #pragma unroll
    for (int off = 16; off; off >>= 1) s += __shfl_down_sync(~0u, s, off);
    if ((t & 31) == 0) red[t >> 5] = s;
    __syncthreads();
    if (t == 0) {
        int tot = 0;
        #pragma unroll
        for (int w = 0; w < 8; w++) tot += red[w];
        g_part[blockIdx.x] = tot;
    }
}

// -------- scan phase B: exclusive scan of <=64 partials (one block) --------
__global__ void k_scanB(int nblk, int n) {
    __shared__ int sm[64];
    int t = threadIdx.x;              // 64 threads
    int v = (t < nblk) ? g_part[t] : 0;
    sm[t] = v;
    __syncthreads();
    #pragma unroll
    for (int off = 1; off < 64; off <<= 1) {
        int u = (t >= off) ? sm[t - off] : 0;
        __syncthreads();
        sm[t] += u;
        __syncthreads();
    }
    if (t < nblk) g_part[t] = (t == 0) ? 0 : sm[t - 1];  // exclusive
    if (t == 63) g_rowptr[n] = sm[63];                   // total = E
}

// -------- scan phase C: block-local scan + offset -> rowptr/fill/dinv --------
__global__ void k_scanC(int n) {
    __shared__ int sm[SCAN_CHUNK];
    int t = threadIdx.x;              // 1024 threads
    int i = blockIdx.x * SCAN_CHUNK + t;
    int d = (i < n) ? g_degi[i] : 0;
    sm[t] = d;
    __syncthreads();
    #pragma unroll
    for (int off = 1; off < SCAN_CHUNK; off <<= 1) {
        int u = (t >= off) ? sm[t - off] : 0;
        __syncthreads();
        sm[t] += u;
        __syncthreads();
    }
    if (i < n) {
        int excl = g_part[blockIdx.x] + sm[t] - d;
        g_rowptr[i] = excl;
        g_fill[i] = excl;
        g_dinv[i] = rsqrtf((float)d + 1.0f);   // +1 self-loop
    }
}

// -------- permute edges into CSR (by dst) --------
__global__ void k_permute(const int* __restrict__ src, const int* __restrict__ dst, int E) {
    int stride = gridDim.x * blockDim.x;
    for (int e = blockIdx.x * blockDim.x + threadIdx.x; e < E; e += stride) {
        int d = dst[e];
        int pos = atomicAdd(&g_fill[d], 1);
        g_csr_src[pos] = src[e];
    }
}

// -------- GEMM: out[n,128] = A[n,128] @ W[128,128] --------
__global__ void k_gemm(const float* __restrict__ A, const float* __restrict__ W,
                       float* __restrict__ out, int n) {
    extern __shared__ float sm[];
    float* Ws = sm;            // 128*128
    float* xs = sm + D * D;    // 16*128
    int t = threadIdx.x;
    for (int i = t; i < (D * D) / 4; i += 128)
        ((float4*)Ws)[i] = ((const float4*)W)[i];
    __syncthreads();

    int lane = t & 31;
    int wg = t >> 5;
    int col = lane * 4;
    int rb = wg * 4;

    for (int r0 = blockIdx.x * 16; r0 < n; r0 += gridDim.x * 16) {
        int rows = n - r0;
        if (rows > 16) rows = 16;
        __syncthreads();
        for (int i = t; i < rows * (D / 4); i += 128)
            ((float4*)xs)[i] = ((const float4*)(A + (size_t)r0 * D))[i];
        __syncthreads();

        float4 a0 = {0,0,0,0}, a1 = {0,0,0,0}, a2 = {0,0,0,0}, a3 = {0,0,0,0};
        #pragma unroll 4
        for (int k = 0; k < D; k++) {
            float4 w = *(const float4*)&Ws[k * D + col];
            float x0 = xs[(rb + 0) * D + k];
            float x1 = xs[(rb + 1) * D + k];
            float x2 = xs[(rb + 2) * D + k];
            float x3 = xs[(rb + 3) * D + k];
            a0.x += x0 * w.x; a0.y += x0 * w.y; a0.z += x0 * w.z; a0.w += x0 * w.w;
            a1.x += x1 * w.x; a1.y += x1 * w.y; a1.z += x1 * w.z; a1.w += x1 * w.w;
            a2.x += x2 * w.x; a2.y += x2 * w.y; a2.z += x2 * w.z; a2.w += x2 * w.w;
            a3.x += x3 * w.x; a3.y += x3 * w.y; a3.z += x3 * w.z; a3.w += x3 * w.w;
        }
        if (rb + 0 < rows) *(float4*)&out[(size_t)(r0 + rb + 0) * D + col] = a0;
        if (rb + 1 < rows) *(float4*)&out[(size_t)(r0 + rb + 1) * D + col] = a1;
        if (rb + 2 < rows) *(float4*)&out[(size_t)(r0 + rb + 2) * D + col] = a2;
        if (rb + 3 < rows) *(float4*)&out[(size_t)(r0 + rb + 3) * D + col] = a3;
    }
}

// -------- CSR gather + combine: out = lrelu(sum coef*h[src] + h*dinv^2 + b) ----
__global__ void k_gcn(const float* __restrict__ h, const float* __restrict__ bias,
                      float* __restrict__ out, int n) {
    int node = blockIdx.x * 8 + (threadIdx.x >> 5);
    if (node >= n) return;
    int lane = threadIdx.x & 31;
    int beg = g_rowptr[node], end = g_rowptr[node + 1];
    float di = g_dinv[node];

    float4 acc = make_float4(0.f, 0.f, 0.f, 0.f);
    for (int e = beg; e < end; e++) {
        int s = g_csr_src[e];
        float coef = g_dinv[s] * di;
        float4 v = ((const float4*)(h + (size_t)s * D))[lane];
        acc.x += coef * v.x; acc.y += coef * v.y;
        acc.z += coef * v.z; acc.w += coef * v.w;
    }
    float4 hv = ((const float4*)(h + (size_t)node * D))[lane];
    float4 b = ((const float4*)bias)[lane];
    float d2 = di * di;
    float4 r;
    r.x = lrelu(acc.x + hv.x * d2 + b.x);
    r.y = lrelu(acc.y + hv.y * d2 + b.y);
    r.z = lrelu(acc.z + hv.z * d2 + b.z);
    r.w = lrelu(acc.w + hv.w * d2 + b.w);
    ((float4*)(out + (size_t)node * D))[lane] = r;
}

// -------- layer-2: CSR gather + combine + pool atomics --------
__global__ void k_gcn_pool(const float* __restrict__ h, const float* __restrict__ bias,
                           const int* __restrict__ batch, int n) {
    int node = blockIdx.x * 8 + (threadIdx.x >> 5);
    if (node >= n) return;
    int lane = threadIdx.x & 31;
    int beg = g_rowptr[node], end = g_rowptr[node + 1];
    float di = g_dinv[node];

    float4 acc = make_float4(0.f, 0.f, 0.f, 0.f);
    for (int e = beg; e < end; e++) {
        int s = g_csr_src[e];
        float coef = g_dinv[s] * di;
        float4 v = ((const float4*)(h + (size_t)s * D))[lane];
        acc.x += coef * v.x; acc.y += coef * v.y;
        acc.z += coef * v.z; acc.w += coef * v.w;
    }
    float4 hv = ((const float4*)(h + (size_t)node * D))[lane];
    float4 b = ((const float4*)bias)[lane];
    float d2 = di * di;
    float4 r;
    r.x = lrelu(acc.x + hv.x * d2 + b.x);
    r.y = lrelu(acc.y + hv.y * d2 + b.y);
    r.z = lrelu(acc.z + hv.z * d2 + b.z);
    r.w = lrelu(acc.w + hv.w * d2 + b.w);
    int gid = batch[node];
    atomicAdd(((float4*)g_pool) + gid * 32 + lane, r);
}

// -------- head: out[g,c] = (pool[g]/cnt[g]) @ Wl + bl --------
__global__ void k_final(const float* __restrict__ Wl, const float* __restrict__ bl,
                        float* __restrict__ out) {
    int t = threadIdx.x;           // 1024 threads, 1 block
    int g = t >> 4;
    int c = t & 15;
    float cnt = fmaxf(g_cnt[g], 1.0f);
    float s = 0.0f;
    #pragma unroll 8
    for (int f = 0; f < D; f++)
        s += g_pool[g * D + f] * Wl[f * CO + c];
    out[g * CO + c] = s / cnt + bl[c];
}

extern "C" void kernel_launch(void* const* d_in, const int* in_sizes, int n_in,
                              void* d_out, int out_size) {
    const float* x     = (const float*)d_in[0];
    const int*   ei    = (const int*)d_in[1];
    const int*   batch = (const int*)d_in[2];
    const float* W1    = (const float*)d_in[3];
    const float* b1    = (const float*)d_in[4];
    const float* W2    = (const float*)d_in[5];
    const float* b2    = (const float*)d_in[6];
    const float* Wl    = (const float*)d_in[7];
    const float* bl    = (const float*)d_in[8];

    int n = in_sizes[0] / D;
    int E = in_sizes[1] / 2;
    const int* src = ei;
    const int* dst = ei + E;

    void *ph1 = nullptr, *ph2 = nullptr;
    cudaGetSymbolAddress(&ph1, g_h1);
    cudaGetSymbolAddress(&ph2, g_h2);
    float* h1 = (float*)ph1;
    float* h2 = (float*)ph2;

    int smem = (D * D + 16 * D) * (int)sizeof(float);  // 73728 B
    cudaFuncSetAttribute(k_gemm, cudaFuncAttributeMaxDynamicSharedMemorySize, smem);

    int nblk = (n + SCAN_CHUNK - 1) / SCAN_CHUNK;   // <= 49
    int nblocks8 = (n + 7) / 8;

    // CSR build (all phases full-chip parallel)
    k_init<<<512, 256>>>(batch, n);
    k_hist<<<1024, 256>>>(dst, E);
    k_cnt<<<256, 256>>>(batch, n);
    k_scanA<<<nblk, 256>>>(n);
    k_scanB<<<1, 64>>>(nblk, n);
    k_scanC<<<nblk, SCAN_CHUNK>>>(n);
    k_permute<<<1024, 256>>>(src, dst, E);

    // Layer 1: h1 = x@W1 ; h2 = gcn(h1)
    k_gemm<<<444, 128, smem>>>(x, W1, h1, n);
    k_gcn<<<nblocks8, 256>>>(h1, b1, h2, n);

    // Layer 2: h1 = h2@W2 ; pool += gcn(h1)
    k_gemm<<<444, 128, smem>>>(h2, W2, h1, n);
    k_gcn_pool<<<nblocks8, 256>>>(h1, b2, batch, n);

    // Head
    k_final<<<1, 1024>>>(Wl, bl, (float*)d_out);
}

// round 6
// speedup vs baseline: 2.0233x; 1.0987x over previous
#include <cuda_runtime.h>
#include <cstdint>

#define D 128
#define NG 64
#define CO 16
#define MAXN 50176
#define MAXE 600064
#define NEG 0.1f
#define SCAN_CHUNK 1024
#define AST 132   // padded smem row stride (floats)

// -------- scratch (device globals: allocation-free workaround) --------
__device__ float g_h1[MAXN * D];
__device__ float g_h2[MAXN * D];
__device__ float g_Bhi[D * D];
__device__ float g_Blo[D * D];
__device__ float g_dinv[MAXN];
__device__ int   g_degi[MAXN];
__device__ int   g_rowptr[MAXN + 1];
__device__ int   g_fill[MAXN];
__device__ int   g_csr_src[MAXE];
__device__ int   g_part[64];
__device__ float g_pool[NG * D];
__device__ float g_cnt[NG];

__device__ __forceinline__ float lrelu(float v) {
    return v >= 0.0f ? v : NEG * v;
}
__device__ __forceinline__ uint32_t tf32bits(float x) {
    uint32_t u;
    asm("cvt.rna.tf32.f32 %0, %1;" : "=r"(u) : "f"(x));
    return u;
}
__device__ __forceinline__ void mma8(float* c, const uint32_t* a, uint32_t b0, uint32_t b1) {
    asm volatile(
        "mma.sync.aligned.m16n8k8.row.col.f32.tf32.tf32.f32 "
        "{%0,%1,%2,%3}, {%4,%5,%6,%7}, {%8,%9}, {%0,%1,%2,%3};"
        : "+f"(c[0]), "+f"(c[1]), "+f"(c[2]), "+f"(c[3])
        : "r"(a[0]), "r"(a[1]), "r"(a[2]), "r"(a[3]), "r"(b0), "r"(b1));
}

// -------- W split: Bhi/Blo[n,k] = tf32-split of W[k,n] --------
__global__ void k_tr(const float* __restrict__ W,
                     float* __restrict__ BH, float* __restrict__ BL) {
    int i = blockIdx.x * 256 + threadIdx.x;   // 16384 total
    int nn = i >> 7, k = i & 127;
    float w = W[k * D + nn];
    float hi = __uint_as_float(tf32bits(w));
    BH[i] = hi;
    BL[i] = __uint_as_float(tf32bits(w - hi));
}

// ===================== tf32x3 HMMA GEMM =====================
// out[n,128] = A[n,128] @ W[128,128]. One CTA per 128-row tile, 8 warps,
// warp w owns rows w*16..w*16+15 x all 128 cols. m16n8k8 fragments.
__global__ void __launch_bounds__(256, 1)
k_gemm_mma(const float* __restrict__ A, const float* __restrict__ BhiG,
           const float* __restrict__ BloG, float* __restrict__ out, int n) {
    extern __shared__ float sm[];
    float* As = sm;                 // 128 x AST
    float* Bh = sm + 128 * AST;     // 128 x AST   [n][k], tf32-rounded
    float* Bl = Bh + 128 * AST;     // 128 x AST

    int t = threadIdx.x;
    int r0 = blockIdx.x * 128;
    int rows = n - r0;
    if (rows > 128) rows = 128;

    const float4* A4 = (const float4*)(A + (size_t)r0 * D);
    for (int i = t; i < 128 * 32; i += 256) {
        int row = i >> 5, c4 = i & 31;
        float4 v = (row < rows) ? A4[row * 32 + c4] : make_float4(0.f, 0.f, 0.f, 0.f);
        *(float4*)&As[row * AST + c4 * 4] = v;
        *(float4*)&Bh[row * AST + c4 * 4] = ((const float4*)BhiG)[i];
        *(float4*)&Bl[row * AST + c4 * 4] = ((const float4*)BloG)[i];
    }
    __syncthreads();

    int wid = t >> 5, lane = t & 31;
    int gid = lane >> 2, tig = lane & 3;
    int wrow = wid * 16;

    float acc[16][4];
    #pragma unroll
    for (int nt = 0; nt < 16; nt++)
        #pragma unroll
        for (int q = 0; q < 4; q++) acc[nt][q] = 0.0f;

    const float* arow0 = &As[(wrow + gid) * AST];
    const float* arow1 = &As[(wrow + gid + 8) * AST];

    #pragma unroll 1
    for (int k8 = 0; k8 < D; k8 += 8) {
        float a0 = arow0[k8 + tig];
        float a1 = arow1[k8 + tig];
        float a2 = arow0[k8 + tig + 4];
        float a3 = arow1[k8 + tig + 4];
        uint32_t ah[4], al[4];
        ah[0] = tf32bits(a0); al[0] = tf32bits(a0 - __uint_as_float(ah[0]));
        ah[1] = tf32bits(a1); al[1] = tf32bits(a1 - __uint_as_float(ah[1]));
        ah[2] = tf32bits(a2); al[2] = tf32bits(a2 - __uint_as_float(ah[2]));
        ah[3] = tf32bits(a3); al[3] = tf32bits(a3 - __uint_as_float(ah[3]));

        #pragma unroll
        for (int nt = 0; nt < 16; nt++) {
            const float* bbase = &Bh[(nt * 8 + gid) * AST + k8];
            uint32_t bh0 = __float_as_uint(bbase[tig]);
            uint32_t bh1 = __float_as_uint(bbase[tig + 4]);
            const float* lbase = &Bl[(nt * 8 + gid) * AST + k8];
            uint32_t bl0 = __float_as_uint(lbase[tig]);
            uint32_t bl1 = __float_as_uint(lbase[tig + 4]);
            mma8(acc[nt], ah, bh0, bh1);   // hi*hi
            mma8(acc[nt], al, bh0, bh1);   // lo*hi
            mma8(acc[nt], ah, bl0, bl1);   // hi*lo
        }
    }

    // epilogue: c0->C[gid][2*tig], c1->+1, c2->C[gid+8][2*tig], c3->+1
    int m0 = wrow + gid, m1 = wrow + gid + 8;
    float* o0 = out + (size_t)(r0 + m0) * D;
    float* o1 = out + (size_t)(r0 + m1) * D;
    #pragma unroll
    for (int nt = 0; nt < 16; nt++) {
        int c = nt * 8 + tig * 2;
        if (m0 < rows) *(float2*)&o0[c] = make_float2(acc[nt][0], acc[nt][1]);
        if (m1 < rows) *(float2*)&o1[c] = make_float2(acc[nt][2], acc[nt][3]);
    }
}

// ===================== CSR build =====================
__global__ void k_init(int n) {
    int stride = gridDim.x * blockDim.x;
    int i0 = blockIdx.x * blockDim.x + threadIdx.x;
    for (int i = i0; i < n; i += stride) g_degi[i] = 0;
    for (int i = i0; i < NG * D; i += stride) g_pool[i] = 0.0f;
    for (int i = i0; i < NG; i += stride) g_cnt[i] = 0.0f;
}

__global__ void k_hist(const int* __restrict__ dst, int E) {
    int stride = gridDim.x * blockDim.x;
    for (int e = blockIdx.x * blockDim.x + threadIdx.x; e < E; e += stride)
        atomicAdd(&g_degi[dst[e]], 1);
}

__global__ void k_cnt(const int* __restrict__ batch, int n) {
    int stride = gridDim.x * blockDim.x;
    for (int i = blockIdx.x * blockDim.x + threadIdx.x; i < n; i += stride)
        atomicAdd(&g_cnt[batch[i]], 1.0f);
}

__global__ void k_scanA(int n) {
    __shared__ int red[8];
    int t = threadIdx.x;
    int base = blockIdx.x * SCAN_CHUNK;
    int s = 0;
    #pragma unroll
    for (int j = 0; j < 4; j++) {
        int i = base + t + j * 256;
        if (i < n) s += g_degi[i];
    }
    #pragma unroll
    for (int off = 16; off; off >>= 1) s += __shfl_down_sync(~0u, s, off);
    if ((t & 31) == 0) red[t >> 5] = s;
    __syncthreads();
    if (t == 0) {
        int tot = 0;
        #pragma unroll
        for (int w = 0; w < 8; w++) tot += red[w];
        g_part[blockIdx.x] = tot;
    }
}

__global__ void k_scanB(int nblk, int n) {
    __shared__ int sm[64];
    int t = threadIdx.x;
    int v = (t < nblk) ? g_part[t] : 0;
    sm[t] = v;
    __syncthreads();
    #pragma unroll
    for (int off = 1; off < 64; off <<= 1) {
        int u = (t >= off) ? sm[t - off] : 0;
        __syncthreads();
        sm[t] += u;
        __syncthreads();
    }
    if (t < nblk) g_part[t] = (t == 0) ? 0 : sm[t - 1];
    if (t == 63) g_rowptr[n] = sm[63];
}

__global__ void k_scanC(int n) {
    __shared__ int sm[SCAN_CHUNK];
    int t = threadIdx.x;
    int i = blockIdx.x * SCAN_CHUNK + t;
    int d = (i < n) ? g_degi[i] : 0;
    sm[t] = d;
    __syncthreads();
    #pragma unroll
    for (int off = 1; off < SCAN_CHUNK; off <<= 1) {
        int u = (t >= off) ? sm[t - off] : 0;
        __syncthreads();
        sm[t] += u;
        __syncthreads();
    }
    if (i < n) {
        int excl = g_part[blockIdx.x] + sm[t] - d;
        g_rowptr[i] = excl;
        g_fill[i] = excl;
        g_dinv[i] = rsqrtf((float)d + 1.0f);
    }
}

__global__ void k_permute(const int* __restrict__ src, const int* __restrict__ dst, int E) {
    int stride = gridDim.x * blockDim.x;
    for (int e = blockIdx.x * blockDim.x + threadIdx.x; e < E; e += stride) {
        int d = dst[e];
        int pos = atomicAdd(&g_fill[d], 1);
        g_csr_src[pos] = src[e];
    }
}

// ===================== gather / pool / head =====================
__global__ void k_gcn(const float* __restrict__ h, const float* __restrict__ bias,
                      float* __restrict__ out, int n) {
    int node = blockIdx.x * 8 + (threadIdx.x >> 5);
    if (node >= n) return;
    int lane = threadIdx.x & 31;
    int beg = g_rowptr[node], end = g_rowptr[node + 1];
    float di = g_dinv[node];

    float4 acc = make_float4(0.f, 0.f, 0.f, 0.f);
    for (int e = beg; e < end; e++) {
        int s = g_csr_src[e];
        float coef = g_dinv[s] * di;
        float4 v = ((const float4*)(h + (size_t)s * D))[lane];
        acc.x += coef * v.x; acc.y += coef * v.y;
        acc.z += coef * v.z; acc.w += coef * v.w;
    }
    float4 hv = ((const float4*)(h + (size_t)node * D))[lane];
    float4 b = ((const float4*)bias)[lane];
    float d2 = di * di;
    float4 r;
    r.x = lrelu(acc.x + hv.x * d2 + b.x);
    r.y = lrelu(acc.y + hv.y * d2 + b.y);
    r.z = lrelu(acc.z + hv.z * d2 + b.z);
    r.w = lrelu(acc.w + hv.w * d2 + b.w);
    ((float4*)(out + (size_t)node * D))[lane] = r;
}

__global__ void k_gcn_pool(const float* __restrict__ h, const float* __restrict__ bias,
                           const int* __restrict__ batch, int n) {
    int node = blockIdx.x * 8 + (threadIdx.x >> 5);
    if (node >= n) return;
    int lane = threadIdx.x & 31;
    int beg = g_rowptr[node], end = g_rowptr[node + 1];
    float di = g_dinv[node];

    float4 acc = make_float4(0.f, 0.f, 0.f, 0.f);
    for (int e = beg; e < end; e++) {
        int s = g_csr_src[e];
        float coef = g_dinv[s] * di;
        float4 v = ((const float4*)(h + (size_t)s * D))[lane];
        acc.x += coef * v.x; acc.y += coef * v.y;
        acc.z += coef * v.z; acc.w += coef * v.w;
    }
    float4 hv = ((const float4*)(h + (size_t)node * D))[lane];
    float4 b = ((const float4*)bias)[lane];
    float d2 = di * di;
    float4 r;
    r.x = lrelu(acc.x + hv.x * d2 + b.x);
    r.y = lrelu(acc.y + hv.y * d2 + b.y);
    r.z = lrelu(acc.z + hv.z * d2 + b.z);
    r.w = lrelu(acc.w + hv.w * d2 + b.w);
    int gid = batch[node];
    atomicAdd(((float4*)g_pool) + gid * 32 + lane, r);
}

__global__ void k_final(const float* __restrict__ Wl, const float* __restrict__ bl,
                        float* __restrict__ out) {
    int t = threadIdx.x;
    int g = t >> 4;
    int c = t & 15;
    float cnt = fmaxf(g_cnt[g], 1.0f);
    float s = 0.0f;
    #pragma unroll 8
    for (int f = 0; f < D; f++)
        s += g_pool[g * D + f] * Wl[f * CO + c];
    out[g * CO + c] = s / cnt + bl[c];
}

extern "C" void kernel_launch(void* const* d_in, const int* in_sizes, int n_in,
                              void* d_out, int out_size) {
    const float* x     = (const float*)d_in[0];
    const int*   ei    = (const int*)d_in[1];
    const int*   batch = (const int*)d_in[2];
    const float* W1    = (const float*)d_in[3];
    const float* b1    = (const float*)d_in[4];
    const float* W2    = (const float*)d_in[5];
    const float* b2    = (const float*)d_in[6];
    const float* Wl    = (const float*)d_in[7];
    const float* bl    = (const float*)d_in[8];

    int n = in_sizes[0] / D;
    int E = in_sizes[1] / 2;
    const int* src = ei;
    const int* dst = ei + E;

    void *ph1 = nullptr, *ph2 = nullptr, *pbh = nullptr, *pbl = nullptr;
    cudaGetSymbolAddress(&ph1, g_h1);
    cudaGetSymbolAddress(&ph2, g_h2);
    cudaGetSymbolAddress(&pbh, g_Bhi);
    cudaGetSymbolAddress(&pbl, g_Blo);
    float* h1 = (float*)ph1;
    float* h2 = (float*)ph2;
    float* BH = (float*)pbh;
    float* BL = (float*)pbl;

    int smem = 3 * 128 * AST * (int)sizeof(float);   // 202752 B
    cudaFuncSetAttribute(k_gemm_mma, cudaFuncAttributeMaxDynamicSharedMemorySize, smem);

    int nblk = (n + SCAN_CHUNK - 1) / SCAN_CHUNK;
    int nblocks8 = (n + 7) / 8;
    int gtiles = (n + 127) / 128;

    // CSR build
    k_init<<<512, 256>>>(n);
    k_hist<<<1024, 256>>>(dst, E);
    k_cnt<<<256, 256>>>(batch, n);
    k_scanA<<<nblk, 256>>>(n);
    k_scanB<<<1, 64>>>(nblk, n);
    k_scanC<<<nblk, SCAN_CHUNK>>>(n);
    k_permute<<<1024, 256>>>(src, dst, E);

    // Layer 1: h1 = x@W1 ; h2 = gcn(h1)
    k_tr<<<64, 256>>>(W1, BH, BL);
    k_gemm_mma<<<gtiles, 256, smem>>>(x, BH, BL, h1, n);
    k_gcn<<<nblocks8, 256>>>(h1, b1, h2, n);

    // Layer 2: h1 = h2@W2 ; pool += gcn(h1)
    k_tr<<<64, 256>>>(W2, BH, BL);
    k_gemm_mma<<<gtiles, 256, smem>>>(h2, BH, BL, h1, n);
    k_gcn_pool<<<nblocks8, 256>>>(h1, b2, batch, n);

    // Head
    k_final<<<1, 1024>>>(Wl, bl, (float*)d_out);
}